// round 9
// baseline (speedup 1.0000x reference)
#include <cuda_runtime.h>
#include <cuda_bf16.h>

// Problem constants
#define NN 10000
#define DD 256
#define HH 512
#define EE 320000

// Scratch (device globals: allocation-free rule)
__device__ float4 g_agg[NN * (DD / 4)];   // [N, 256]  aggregated messages
__device__ float4 g_h  [NN * (HH / 4)];   // [N, 512]  relu(cat @ W_conv + b)

// ---------------------------------------------------------------------------
__global__ void k_zero_agg() {
    int i = blockIdx.x * blockDim.x + threadIdx.x;
    if (i < NN * (DD / 4)) g_agg[i] = make_float4(0.f, 0.f, 0.f, 0.f);
}

__global__ void k_init_out(float* __restrict__ out, const float* __restrict__ b2) {
    int i = blockIdx.x * blockDim.x + threadIdx.x;
    if (i < NN) out[i] = b2[0];
}

// SpMM scatter: agg[dst] += x[src] * val   (one warp per edge, float4 atomics)
__global__ void k_scatter(const float4* __restrict__ x4,
                          const int*    __restrict__ esrc,
                          const int*    __restrict__ edst,
                          const float*  __restrict__ eval) {
    int gid  = blockIdx.x * blockDim.x + threadIdx.x;
    int w    = gid >> 5;
    int lane = gid & 31;
    if (w >= EE) return;
    int   s = __ldg(esrc + w);
    int   d = __ldg(edst + w);
    float v = __ldg(eval + w);
    const float4* xr = x4    + (size_t)s * (DD / 4);
    float4*       ar = g_agg + (size_t)d * (DD / 4);
    #pragma unroll
    for (int j = 0; j < 2; j++) {
        int c = lane + j * 32;
        float4 t = __ldg(xr + c);
        t.x *= v; t.y *= v; t.z *= v; t.w *= v;
        atomicAdd(ar + c, t);
    }
}

// ---------------------------------------------------------------------------
// SIMT fp32 GEMM, 128x128 tile, BK=16, 256 threads, 8x8 per thread,
// TWO-STAGE smem double buffer with register prefetch: LDGs for chunk kc+1
// issue before computing chunk kc, so L2 latency overlaps the 512-cycle
// FFMA block instead of being exposed at the barrier.
#define BM 128
#define BN 128
#define BK 16

// GEMM1: h = relu( [x | agg] @ W_conv + b_conv )    A:[N,512] B:[512,512]
__global__ __launch_bounds__(256)
void k_gemm1(const float* __restrict__ x,
             const float* __restrict__ Wc,
             const float* __restrict__ bc) {
    __shared__ float As[2][BK][BM];
    __shared__ float Bs[2][BK][BN];

    const int tid = threadIdx.x;
    const int tx = tid & 15;
    const int ty = tid >> 4;
    const int rowBase = blockIdx.y * BM;
    const int colBase = blockIdx.x * BN;

    const int la_row = tid >> 2;          // 0..63
    const int la_kc  = (tid & 3) * 4;     // 0,4,8,12
    const int lb_k   = tid >> 4;          // 0..15
    const int lb_nc  = (tid & 15) * 4;    // 0..60

    const float* aggf = (const float*)g_agg;
    const int NCH = (2 * DD) / BK;        // 32 chunks

    float acc[8][8];
    #pragma unroll
    for (int i = 0; i < 8; i++)
        #pragma unroll
        for (int j = 0; j < 8; j++) acc[i][j] = 0.f;

    float4 pa0, pa1, pb0, pb1;

    // prefetch chunk 0
    {
        const float* Asrc = x;
        int gr0 = rowBase + la_row;
        int gr1 = gr0 + 64;
        pa0 = (gr0 < NN) ? *(const float4*)(Asrc + (size_t)gr0 * DD + la_kc)
                         : make_float4(0.f, 0.f, 0.f, 0.f);
        pa1 = (gr1 < NN) ? *(const float4*)(Asrc + (size_t)gr1 * DD + la_kc)
                         : make_float4(0.f, 0.f, 0.f, 0.f);
        pb0 = *(const float4*)(Wc + (size_t)lb_k * HH + colBase + lb_nc);
        pb1 = *(const float4*)(Wc + (size_t)lb_k * HH + colBase + lb_nc + 64);
    }
    // store chunk 0 -> buf 0
    As[0][la_kc + 0][la_row] = pa0.x; As[0][la_kc + 1][la_row] = pa0.y;
    As[0][la_kc + 2][la_row] = pa0.z; As[0][la_kc + 3][la_row] = pa0.w;
    As[0][la_kc + 0][la_row + 64] = pa1.x; As[0][la_kc + 1][la_row + 64] = pa1.y;
    As[0][la_kc + 2][la_row + 64] = pa1.z; As[0][la_kc + 3][la_row + 64] = pa1.w;
    *(float4*)&Bs[0][lb_k][lb_nc]      = pb0;
    *(float4*)&Bs[0][lb_k][lb_nc + 64] = pb1;
    __syncthreads();

    for (int kc = 0; kc < NCH; kc++) {
        const int cur = kc & 1;
        // prefetch chunk kc+1 (LDGs overlap the compute below)
        if (kc + 1 < NCH) {
            const int kt = (kc + 1) * BK;
            const float* Asrc = (kt < DD) ? x : aggf;
            const int kk0 = kt & (DD - 1);
            int gr0 = rowBase + la_row;
            int gr1 = gr0 + 64;
            pa0 = (gr0 < NN) ? *(const float4*)(Asrc + (size_t)gr0 * DD + kk0 + la_kc)
                             : make_float4(0.f, 0.f, 0.f, 0.f);
            pa1 = (gr1 < NN) ? *(const float4*)(Asrc + (size_t)gr1 * DD + kk0 + la_kc)
                             : make_float4(0.f, 0.f, 0.f, 0.f);
            pb0 = *(const float4*)(Wc + (size_t)(kt + lb_k) * HH + colBase + lb_nc);
            pb1 = *(const float4*)(Wc + (size_t)(kt + lb_k) * HH + colBase + lb_nc + 64);
        }

        #pragma unroll
        for (int kk = 0; kk < BK; kk++) {
            float4 a0 = *(const float4*)&As[cur][kk][ty * 4];
            float4 a1 = *(const float4*)&As[cur][kk][64 + ty * 4];
            float4 b0 = *(const float4*)&Bs[cur][kk][tx * 4];
            float4 b1 = *(const float4*)&Bs[cur][kk][64 + tx * 4];
            float a[8] = {a0.x, a0.y, a0.z, a0.w, a1.x, a1.y, a1.z, a1.w};
            float b[8] = {b0.x, b0.y, b0.z, b0.w, b1.x, b1.y, b1.z, b1.w};
            #pragma unroll
            for (int i = 0; i < 8; i++)
                #pragma unroll
                for (int j = 0; j < 8; j++)
                    acc[i][j] = fmaf(a[i], b[j], acc[i][j]);
        }

        if (kc + 1 < NCH) {
            const int nxt = (kc + 1) & 1;
            As[nxt][la_kc + 0][la_row] = pa0.x; As[nxt][la_kc + 1][la_row] = pa0.y;
            As[nxt][la_kc + 2][la_row] = pa0.z; As[nxt][la_kc + 3][la_row] = pa0.w;
            As[nxt][la_kc + 0][la_row + 64] = pa1.x; As[nxt][la_kc + 1][la_row + 64] = pa1.y;
            As[nxt][la_kc + 2][la_row + 64] = pa1.z; As[nxt][la_kc + 3][la_row + 64] = pa1.w;
            *(float4*)&Bs[nxt][lb_k][lb_nc]      = pb0;
            *(float4*)&Bs[nxt][lb_k][lb_nc + 64] = pb1;
            __syncthreads();
        }
    }

    // epilogue: + bias, relu, store h (two float4 per row-slot)
    float* hf = (float*)g_h;
    const float4 bias0 = *(const float4*)(bc + colBase + tx * 4);
    const float4 bias1 = *(const float4*)(bc + colBase + 64 + tx * 4);
    #pragma unroll
    for (int i = 0; i < 8; i++) {
        int r = rowBase + (i < 4 ? ty * 4 + i : 64 + ty * 4 + (i - 4));
        if (r < NN) {
            float4 o0, o1;
            o0.x = fmaxf(acc[i][0] + bias0.x, 0.f);
            o0.y = fmaxf(acc[i][1] + bias0.y, 0.f);
            o0.z = fmaxf(acc[i][2] + bias0.z, 0.f);
            o0.w = fmaxf(acc[i][3] + bias0.w, 0.f);
            o1.x = fmaxf(acc[i][4] + bias1.x, 0.f);
            o1.y = fmaxf(acc[i][5] + bias1.y, 0.f);
            o1.z = fmaxf(acc[i][6] + bias1.z, 0.f);
            o1.w = fmaxf(acc[i][7] + bias1.w, 0.f);
            *(float4*)(hf + (size_t)r * HH + colBase + tx * 4)      = o0;
            *(float4*)(hf + (size_t)r * HH + colBase + 64 + tx * 4) = o1;
        }
    }
}

// GEMM2 (fused head): z = prelu(h @ W1 + b1); out[r] += sum_c z[r,c]*W2[c]
__global__ __launch_bounds__(256)
void k_gemm2(const float* __restrict__ W1,
             const float* __restrict__ b1,
             const float* __restrict__ pa,
             const float* __restrict__ W2,
             float* __restrict__ out) {
    __shared__ float As[2][BK][BM];
    __shared__ float Bs[2][BK][BN];

    const int tid = threadIdx.x;
    const int tx = tid & 15;
    const int ty = tid >> 4;
    const int rowBase = blockIdx.y * BM;
    const int colBase = blockIdx.x * BN;

    const int la_row = tid >> 2;
    const int la_kc  = (tid & 3) * 4;
    const int lb_k   = tid >> 4;
    const int lb_nc  = (tid & 15) * 4;

    const float* hf = (const float*)g_h;
    const int NCH = HH / BK;              // 32 chunks

    float acc[8][8];
    #pragma unroll
    for (int i = 0; i < 8; i++)
        #pragma unroll
        for (int j = 0; j < 8; j++) acc[i][j] = 0.f;

    float4 pa0, pa1, pb0, pb1;

    // prefetch chunk 0
    {
        int gr0 = rowBase + la_row;
        int gr1 = gr0 + 64;
        pa0 = (gr0 < NN) ? *(const float4*)(hf + (size_t)gr0 * HH + la_kc)
                         : make_float4(0.f, 0.f, 0.f, 0.f);
        pa1 = (gr1 < NN) ? *(const float4*)(hf + (size_t)gr1 * HH + la_kc)
                         : make_float4(0.f, 0.f, 0.f, 0.f);
        pb0 = *(const float4*)(W1 + (size_t)lb_k * HH + colBase + lb_nc);
        pb1 = *(const float4*)(W1 + (size_t)lb_k * HH + colBase + lb_nc + 64);
    }
    As[0][la_kc + 0][la_row] = pa0.x; As[0][la_kc + 1][la_row] = pa0.y;
    As[0][la_kc + 2][la_row] = pa0.z; As[0][la_kc + 3][la_row] = pa0.w;
    As[0][la_kc + 0][la_row + 64] = pa1.x; As[0][la_kc + 1][la_row + 64] = pa1.y;
    As[0][la_kc + 2][la_row + 64] = pa1.z; As[0][la_kc + 3][la_row + 64] = pa1.w;
    *(float4*)&Bs[0][lb_k][lb_nc]      = pb0;
    *(float4*)&Bs[0][lb_k][lb_nc + 64] = pb1;
    __syncthreads();

    for (int kc = 0; kc < NCH; kc++) {
        const int cur = kc & 1;
        if (kc + 1 < NCH) {
            const int kt = (kc + 1) * BK;
            int gr0 = rowBase + la_row;
            int gr1 = gr0 + 64;
            pa0 = (gr0 < NN) ? *(const float4*)(hf + (size_t)gr0 * HH + kt + la_kc)
                             : make_float4(0.f, 0.f, 0.f, 0.f);
            pa1 = (gr1 < NN) ? *(const float4*)(hf + (size_t)gr1 * HH + kt + la_kc)
                             : make_float4(0.f, 0.f, 0.f, 0.f);
            pb0 = *(const float4*)(W1 + (size_t)(kt + lb_k) * HH + colBase + lb_nc);
            pb1 = *(const float4*)(W1 + (size_t)(kt + lb_k) * HH + colBase + lb_nc + 64);
        }

        #pragma unroll
        for (int kk = 0; kk < BK; kk++) {
            float4 a0 = *(const float4*)&As[cur][kk][ty * 4];
            float4 a1 = *(const float4*)&As[cur][kk][64 + ty * 4];
            float4 b0 = *(const float4*)&Bs[cur][kk][tx * 4];
            float4 b1 = *(const float4*)&Bs[cur][kk][64 + tx * 4];
            float a[8] = {a0.x, a0.y, a0.z, a0.w, a1.x, a1.y, a1.z, a1.w};
            float b[8] = {b0.x, b0.y, b0.z, b0.w, b1.x, b1.y, b1.z, b1.w};
            #pragma unroll
            for (int i = 0; i < 8; i++)
                #pragma unroll
                for (int j = 0; j < 8; j++)
                    acc[i][j] = fmaf(a[i], b[j], acc[i][j]);
        }

        if (kc + 1 < NCH) {
            const int nxt = (kc + 1) & 1;
            As[nxt][la_kc + 0][la_row] = pa0.x; As[nxt][la_kc + 1][la_row] = pa0.y;
            As[nxt][la_kc + 2][la_row] = pa0.z; As[nxt][la_kc + 3][la_row] = pa0.w;
            As[nxt][la_kc + 0][la_row + 64] = pa1.x; As[nxt][la_kc + 1][la_row + 64] = pa1.y;
            As[nxt][la_kc + 2][la_row + 64] = pa1.z; As[nxt][la_kc + 3][la_row + 64] = pa1.w;
            *(float4*)&Bs[nxt][lb_k][lb_nc]      = pb0;
            *(float4*)&Bs[nxt][lb_k][lb_nc + 64] = pb1;
            __syncthreads();
        }
    }

    // epilogue: bias, PReLU, dot with W2, reduce across 16 col-threads, atomic
    const float4 b1v0 = *(const float4*)(b1 + colBase + tx * 4);
    const float4 b1v1 = *(const float4*)(b1 + colBase + 64 + tx * 4);
    const float4 pav0 = *(const float4*)(pa + colBase + tx * 4);
    const float4 pav1 = *(const float4*)(pa + colBase + 64 + tx * 4);
    const float4 w2v0 = *(const float4*)(W2 + colBase + tx * 4);
    const float4 w2v1 = *(const float4*)(W2 + colBase + 64 + tx * 4);

    const float bz[8] = {b1v0.x, b1v0.y, b1v0.z, b1v0.w, b1v1.x, b1v1.y, b1v1.z, b1v1.w};
    const float pv[8] = {pav0.x, pav0.y, pav0.z, pav0.w, pav1.x, pav1.y, pav1.z, pav1.w};
    const float wv[8] = {w2v0.x, w2v0.y, w2v0.z, w2v0.w, w2v1.x, w2v1.y, w2v1.z, w2v1.w};

    #pragma unroll
    for (int i = 0; i < 8; i++) {
        float s = 0.f;
        #pragma unroll
        for (int j = 0; j < 8; j++) {
            float z = acc[i][j] + bz[j];
            z = z > 0.f ? z : pv[j] * z;
            s = fmaf(z, wv[j], s);
        }
        #pragma unroll
        for (int m = 8; m > 0; m >>= 1)
            s += __shfl_xor_sync(0xffffffffu, s, m);
        if (tx == 0) {
            int r = rowBase + (i < 4 ? ty * 4 + i : 64 + ty * 4 + (i - 4));
            if (r < NN) atomicAdd(out + r, s);
        }
    }
}

// ---------------------------------------------------------------------------
extern "C" void kernel_launch(void* const* d_in, const int* in_sizes, int n_in,
                              void* d_out, int out_size) {
    const float* x     = (const float*)d_in[0];
    const int*   esrc  = (const int*)  d_in[1];
    const int*   edst  = (const int*)  d_in[2];
    const float* eval  = (const float*)d_in[3];
    const float* Wc    = (const float*)d_in[4];
    const float* bc    = (const float*)d_in[5];
    const float* W1    = (const float*)d_in[6];
    const float* b1    = (const float*)d_in[7];
    const float* pa    = (const float*)d_in[8];
    const float* W2    = (const float*)d_in[9];
    const float* b2    = (const float*)d_in[10];
    float* out = (float*)d_out;

    // 1) zero agg + seed out with b2
    k_zero_agg<<<(NN * (DD / 4) + 255) / 256, 256>>>();
    k_init_out<<<(NN + 255) / 256, 256>>>(out, b2);

    // 2) SpMM scatter (warp per edge)
    {
        long threads = (long)EE * 32;
        int blocks = (int)((threads + 255) / 256);
        k_scatter<<<blocks, 256>>>((const float4*)x, esrc, edst, eval);
    }

    // 3) GEMM1: h = relu([x|agg] @ W_conv + b_conv)
    {
        dim3 grid(HH / BN, (NN + BM - 1) / BM);
        k_gemm1<<<grid, 256>>>(x, Wc, bc);
    }

    // 4) GEMM2 fused with PReLU + W2 matvec head
    {
        dim3 grid(HH / BN, (NN + BM - 1) / BM);
        k_gemm2<<<grid, 256>>>(W1, b1, pa, W2, out);
    }
}

// round 14
// speedup vs baseline: 1.2054x; 1.2054x over previous
#include <cuda_runtime.h>
#include <cuda_bf16.h>
#include <cstdint>

// Problem constants
#define NN 10000
#define DD 256
#define HH 512
#define EE 320000

// Scratch (device globals: allocation-free rule; ~30MB proven-safe footprint)
__device__ float4 g_agg[NN * (DD / 4)];   // [N, 256]  aggregated messages
__device__ float4 g_h  [NN * (HH / 4)];   // [N, 512]  relu(cat @ W_conv + b)

// ---------------------------------------------------------------------------
__global__ void k_zero_agg() {
    int i = blockIdx.x * blockDim.x + threadIdx.x;
    if (i < NN * (DD / 4)) g_agg[i] = make_float4(0.f, 0.f, 0.f, 0.f);
}

__global__ void k_init_out(float* __restrict__ out, const float* __restrict__ b2) {
    int i = blockIdx.x * blockDim.x + threadIdx.x;
    if (i < NN) out[i] = b2[0];
}

// SpMM scatter: agg[dst] += x[src] * val   (one warp per edge, float4 atomics)
__global__ void k_scatter(const float4* __restrict__ x4,
                          const int*    __restrict__ esrc,
                          const int*    __restrict__ edst,
                          const float*  __restrict__ eval) {
    int gid  = blockIdx.x * blockDim.x + threadIdx.x;
    int w    = gid >> 5;
    int lane = gid & 31;
    if (w >= EE) return;
    int   s = __ldg(esrc + w);
    int   d = __ldg(edst + w);
    float v = __ldg(eval + w);
    const float4* xr = x4    + (size_t)s * (DD / 4);
    float4*       ar = g_agg + (size_t)d * (DD / 4);
    #pragma unroll
    for (int j = 0; j < 2; j++) {
        int c = lane + j * 32;
        float4 t = __ldg(xr + c);
        t.x *= v; t.y *= v; t.z *= v; t.w *= v;
        atomicAdd(ar + c, t);
    }
}

// ---------------------------------------------------------------------------
// SIMT fp32 GEMM with PACKED f32x2 FMA (Blackwell: 2 FMAs per issue slot).
// 128x128 tile, BK=16, 256 threads, 8x8 per thread held as 8x4 packed pairs.
#define BM 128
#define BN 128
#define BK 16

// packed helpers
#define SPLAT64(dst, s)  asm("mov.b64 %0, {%1, %1};" : "=l"(dst) : "f"(s))
#define FMA2(acc, ap, bp) \
    asm("fma.rn.f32x2 %0, %1, %2, %0;" : "+l"(acc) : "l"(ap), "l"(bp))
#define UNPACK64(lo, hi, p) \
    asm("mov.b64 {%0, %1}, %2;" : "=f"(lo), "=f"(hi) : "l"(p))

// GEMM1: h = relu( [x | agg] @ W_conv + b_conv )    A:[N,512] B:[512,512]
__global__ __launch_bounds__(256)
void k_gemm1(const float* __restrict__ x,
             const float* __restrict__ Wc,
             const float* __restrict__ bc) {
    __shared__ float As[BK][BM];
    __shared__ float Bs[BK][BN];

    const int tid = threadIdx.x;
    const int tx = tid & 15;
    const int ty = tid >> 4;
    const int rowBase = blockIdx.y * BM;
    const int colBase = blockIdx.x * BN;

    const int la_row = tid >> 2;          // 0..63 (+64 second half)
    const int la_kc  = (tid & 3) * 4;     // 0,4,8,12
    const int lb_k   = tid >> 4;          // 0..15
    const int lb_nc  = (tid & 15) * 4;    // 0..60 (+64 second half)

    const float* aggf = (const float*)g_agg;

    unsigned long long acc[8][4];
    #pragma unroll
    for (int i = 0; i < 8; i++)
        #pragma unroll
        for (int j = 0; j < 4; j++) acc[i][j] = 0ull;

    for (int kt = 0; kt < 2 * DD; kt += BK) {
        const float* Asrc = (kt < DD) ? x : aggf;
        const int kk0 = kt & (DD - 1);
        #pragma unroll
        for (int half = 0; half < 2; half++) {
            int gr = rowBase + la_row + half * 64;
            float4 a4 = make_float4(0.f, 0.f, 0.f, 0.f);
            if (gr < NN)
                a4 = *(const float4*)(Asrc + (size_t)gr * DD + kk0 + la_kc);
            As[la_kc + 0][la_row + half * 64] = a4.x;
            As[la_kc + 1][la_row + half * 64] = a4.y;
            As[la_kc + 2][la_row + half * 64] = a4.z;
            As[la_kc + 3][la_row + half * 64] = a4.w;
        }
        #pragma unroll
        for (int half = 0; half < 2; half++) {
            float4 b4 = *(const float4*)(Wc + (size_t)(kt + lb_k) * HH + colBase + lb_nc + half * 64);
            *(float4*)&Bs[lb_k][lb_nc + half * 64] = b4;
        }
        __syncthreads();

        #pragma unroll
        for (int kk = 0; kk < BK; kk++) {
            float4 a0 = *(const float4*)&As[kk][ty * 4];
            float4 a1 = *(const float4*)&As[kk][64 + ty * 4];
            ulonglong2 bA = *(const ulonglong2*)&Bs[kk][tx * 4];       // pairs (b0,b1),(b2,b3)
            ulonglong2 bB = *(const ulonglong2*)&Bs[kk][64 + tx * 4];  // pairs (b4,b5),(b6,b7)
            float av[8] = {a0.x, a0.y, a0.z, a0.w, a1.x, a1.y, a1.z, a1.w};
            #pragma unroll
            for (int i = 0; i < 8; i++) {
                unsigned long long ap;
                SPLAT64(ap, av[i]);
                FMA2(acc[i][0], ap, bA.x);
                FMA2(acc[i][1], ap, bA.y);
                FMA2(acc[i][2], ap, bB.x);
                FMA2(acc[i][3], ap, bB.y);
            }
        }
        __syncthreads();
    }

    // epilogue: + bias, relu, store h
    float* hf = (float*)g_h;
    const float4 bias0 = *(const float4*)(bc + colBase + tx * 4);
    const float4 bias1 = *(const float4*)(bc + colBase + 64 + tx * 4);
    #pragma unroll
    for (int i = 0; i < 8; i++) {
        int r = rowBase + (i < 4 ? ty * 4 + i : 64 + ty * 4 + (i - 4));
        if (r < NN) {
            float c0, c1, c2, c3, c4, c5, c6, c7;
            UNPACK64(c0, c1, acc[i][0]);
            UNPACK64(c2, c3, acc[i][1]);
            UNPACK64(c4, c5, acc[i][2]);
            UNPACK64(c6, c7, acc[i][3]);
            float4 o0, o1;
            o0.x = fmaxf(c0 + bias0.x, 0.f);
            o0.y = fmaxf(c1 + bias0.y, 0.f);
            o0.z = fmaxf(c2 + bias0.z, 0.f);
            o0.w = fmaxf(c3 + bias0.w, 0.f);
            o1.x = fmaxf(c4 + bias1.x, 0.f);
            o1.y = fmaxf(c5 + bias1.y, 0.f);
            o1.z = fmaxf(c6 + bias1.z, 0.f);
            o1.w = fmaxf(c7 + bias1.w, 0.f);
            *(float4*)(hf + (size_t)r * HH + colBase + tx * 4)      = o0;
            *(float4*)(hf + (size_t)r * HH + colBase + 64 + tx * 4) = o1;
        }
    }
}

// GEMM2 (fused head): z = prelu(h @ W1 + b1); out[r] += sum_c z[r,c]*W2[c]
__global__ __launch_bounds__(256)
void k_gemm2(const float* __restrict__ W1,
             const float* __restrict__ b1,
             const float* __restrict__ pa,
             const float* __restrict__ W2,
             float* __restrict__ out) {
    __shared__ float As[BK][BM];
    __shared__ float Bs[BK][BN];

    const int tid = threadIdx.x;
    const int tx = tid & 15;
    const int ty = tid >> 4;
    const int rowBase = blockIdx.y * BM;
    const int colBase = blockIdx.x * BN;

    const int la_row = tid >> 2;
    const int la_kc  = (tid & 3) * 4;
    const int lb_k   = tid >> 4;
    const int lb_nc  = (tid & 15) * 4;

    const float* hf = (const float*)g_h;

    unsigned long long acc[8][4];
    #pragma unroll
    for (int i = 0; i < 8; i++)
        #pragma unroll
        for (int j = 0; j < 4; j++) acc[i][j] = 0ull;

    for (int kt = 0; kt < HH; kt += BK) {
        #pragma unroll
        for (int half = 0; half < 2; half++) {
            int gr = rowBase + la_row + half * 64;
            float4 a4 = make_float4(0.f, 0.f, 0.f, 0.f);
            if (gr < NN)
                a4 = *(const float4*)(hf + (size_t)gr * HH + kt + la_kc);
            As[la_kc + 0][la_row + half * 64] = a4.x;
            As[la_kc + 1][la_row + half * 64] = a4.y;
            As[la_kc + 2][la_row + half * 64] = a4.z;
            As[la_kc + 3][la_row + half * 64] = a4.w;
        }
        #pragma unroll
        for (int half = 0; half < 2; half++) {
            float4 b4 = *(const float4*)(W1 + (size_t)(kt + lb_k) * HH + colBase + lb_nc + half * 64);
            *(float4*)&Bs[lb_k][lb_nc + half * 64] = b4;
        }
        __syncthreads();

        #pragma unroll
        for (int kk = 0; kk < BK; kk++) {
            float4 a0 = *(const float4*)&As[kk][ty * 4];
            float4 a1 = *(const float4*)&As[kk][64 + ty * 4];
            ulonglong2 bA = *(const ulonglong2*)&Bs[kk][tx * 4];
            ulonglong2 bB = *(const ulonglong2*)&Bs[kk][64 + tx * 4];
            float av[8] = {a0.x, a0.y, a0.z, a0.w, a1.x, a1.y, a1.z, a1.w};
            #pragma unroll
            for (int i = 0; i < 8; i++) {
                unsigned long long ap;
                SPLAT64(ap, av[i]);
                FMA2(acc[i][0], ap, bA.x);
                FMA2(acc[i][1], ap, bA.y);
                FMA2(acc[i][2], ap, bB.x);
                FMA2(acc[i][3], ap, bB.y);
            }
        }
        __syncthreads();
    }

    // epilogue: bias, PReLU, dot with W2, reduce across 16 col-threads, atomic
    const float4 b1v0 = *(const float4*)(b1 + colBase + tx * 4);
    const float4 b1v1 = *(const float4*)(b1 + colBase + 64 + tx * 4);
    const float4 pav0 = *(const float4*)(pa + colBase + tx * 4);
    const float4 pav1 = *(const float4*)(pa + colBase + 64 + tx * 4);
    const float4 w2v0 = *(const float4*)(W2 + colBase + tx * 4);
    const float4 w2v1 = *(const float4*)(W2 + colBase + 64 + tx * 4);

    const float bz[8] = {b1v0.x, b1v0.y, b1v0.z, b1v0.w, b1v1.x, b1v1.y, b1v1.z, b1v1.w};
    const float pv[8] = {pav0.x, pav0.y, pav0.z, pav0.w, pav1.x, pav1.y, pav1.z, pav1.w};
    const float wv[8] = {w2v0.x, w2v0.y, w2v0.z, w2v0.w, w2v1.x, w2v1.y, w2v1.z, w2v1.w};

    #pragma unroll
    for (int i = 0; i < 8; i++) {
        float c[8];
        UNPACK64(c[0], c[1], acc[i][0]);
        UNPACK64(c[2], c[3], acc[i][1]);
        UNPACK64(c[4], c[5], acc[i][2]);
        UNPACK64(c[6], c[7], acc[i][3]);
        float s = 0.f;
        #pragma unroll
        for (int j = 0; j < 8; j++) {
            float z = c[j] + bz[j];
            z = z > 0.f ? z : pv[j] * z;
            s = fmaf(z, wv[j], s);
        }
        #pragma unroll
        for (int m = 8; m > 0; m >>= 1)
            s += __shfl_xor_sync(0xffffffffu, s, m);
        if (tx == 0) {
            int r = rowBase + (i < 4 ? ty * 4 + i : 64 + ty * 4 + (i - 4));
            if (r < NN) atomicAdd(out + r, s);
        }
    }
}

// ---------------------------------------------------------------------------
extern "C" void kernel_launch(void* const* d_in, const int* in_sizes, int n_in,
                              void* d_out, int out_size) {
    const float* x     = (const float*)d_in[0];
    const int*   esrc  = (const int*)  d_in[1];
    const int*   edst  = (const int*)  d_in[2];
    const float* eval  = (const float*)d_in[3];
    const float* Wc    = (const float*)d_in[4];
    const float* bc    = (const float*)d_in[5];
    const float* W1    = (const float*)d_in[6];
    const float* b1    = (const float*)d_in[7];
    const float* pa    = (const float*)d_in[8];
    const float* W2    = (const float*)d_in[9];
    const float* b2    = (const float*)d_in[10];
    float* out = (float*)d_out;

    // 1) zero agg + seed out with b2
    k_zero_agg<<<(NN * (DD / 4) + 255) / 256, 256>>>();
    k_init_out<<<(NN + 255) / 256, 256>>>(out, b2);

    // 2) SpMM scatter (warp per edge)
    {
        long threads = (long)EE * 32;
        int blocks = (int)((threads + 255) / 256);
        k_scatter<<<blocks, 256>>>((const float4*)x, esrc, edst, eval);
    }

    // 3) GEMM1: h = relu([x|agg] @ W_conv + b_conv)
    {
        dim3 grid(HH / BN, (NN + BM - 1) / BM);
        k_gemm1<<<grid, 256>>>(x, Wc, bc);
    }

    // 4) GEMM2 fused with PReLU + W2 matvec head
    {
        dim3 grid(HH / BN, (NN + BM - 1) / BM);
        k_gemm2<<<grid, 256>>>(W1, b1, pa, W2, out);
    }
}